// round 2
// baseline (speedup 1.0000x reference)
#include <cuda_runtime.h>

#define NN 50000
#define NE 800000
#define NG 256
#define FIN 256
#define HD 64

__device__ float g_q[NN * HD];
__device__ float g_k[NN * HD];
__device__ float g_v[NN * HD];
__device__ float g_ex[NE];
__device__ float g_den[NG];

// ---------------------------------------------------------------------------
// Zero the per-graph softmax denominators (256 floats).
// ---------------------------------------------------------------------------
__global__ void zero_den_kernel() { g_den[threadIdx.x] = 0.f; }

// ---------------------------------------------------------------------------
// QKV projection GEMM: out[N,64] = x[N,256] @ W[256,64] + b
// blockIdx.y selects which of {Q,K,V}. BM=128, BN=64, BK=16, 256 threads,
// 8x4 register tile per thread. x tile stored K-major (transposed) in smem
// so the A fragment is two LDS.128 per k-step.
// ---------------------------------------------------------------------------
__global__ __launch_bounds__(256) void qkv_gemm(
    const float* __restrict__ x,
    const float* __restrict__ Wq, const float* __restrict__ bq,
    const float* __restrict__ Wk, const float* __restrict__ bk,
    const float* __restrict__ Wv, const float* __restrict__ bv)
{
    __shared__ __align__(16) float xs[16][132];  // [k][row], padded
    __shared__ __align__(16) float ws[16][64];   // [k][col]

    const float* W; const float* bias; float* out;
    if (blockIdx.y == 0)      { W = Wq; bias = bq; out = g_q; }
    else if (blockIdx.y == 1) { W = Wk; bias = bk; out = g_k; }
    else                      { W = Wv; bias = bv; out = g_v; }

    const int tid = threadIdx.x;
    const int tx = tid & 15;        // output column group (4 cols)
    const int ty = tid >> 4;        // output row group (8 rows)
    const int row0 = blockIdx.x * 128;

    float acc[8][4];
#pragma unroll
    for (int i = 0; i < 8; i++)
#pragma unroll
        for (int j = 0; j < 4; j++) acc[i][j] = 0.f;

    for (int k0 = 0; k0 < FIN; k0 += 16) {
        // Load x tile [128 rows x 16 k] as float4, store transposed.
#pragma unroll
        for (int l = 0; l < 2; l++) {
            int idx = tid + l * 256;
            int r  = idx >> 2;
            int kp = idx & 3;
            int grow = row0 + r;
            float4 f = make_float4(0.f, 0.f, 0.f, 0.f);
            if (grow < NN)
                f = *(const float4*)&x[(size_t)grow * FIN + k0 + kp * 4];
            xs[kp * 4 + 0][r] = f.x;
            xs[kp * 4 + 1][r] = f.y;
            xs[kp * 4 + 2][r] = f.z;
            xs[kp * 4 + 3][r] = f.w;
        }
        // Load W tile [16 k x 64 cols]: one float4 per thread.
        {
            int r  = tid >> 4;
            int c4 = tid & 15;
            *(float4*)&ws[r][c4 * 4] =
                *(const float4*)&W[(size_t)(k0 + r) * HD + c4 * 4];
        }
        __syncthreads();

#pragma unroll
        for (int kk = 0; kk < 16; kk++) {
            float4 a0 = *(const float4*)&xs[kk][ty * 8];
            float4 a1 = *(const float4*)&xs[kk][ty * 8 + 4];
            float4 bb = *(const float4*)&ws[kk][tx * 4];
            float a[8] = {a0.x, a0.y, a0.z, a0.w, a1.x, a1.y, a1.z, a1.w};
            float b[4] = {bb.x, bb.y, bb.z, bb.w};
#pragma unroll
            for (int i = 0; i < 8; i++)
#pragma unroll
                for (int j = 0; j < 4; j++)
                    acc[i][j] += a[i] * b[j];
        }
        __syncthreads();
    }

    float4 bv4 = *(const float4*)&bias[tx * 4];
#pragma unroll
    for (int i = 0; i < 8; i++) {
        int grow = row0 + ty * 8 + i;
        if (grow < NN) {
            float4 o = make_float4(acc[i][0] + bv4.x, acc[i][1] + bv4.y,
                                   acc[i][2] + bv4.z, acc[i][3] + bv4.w);
            *(float4*)&out[(size_t)grow * HD + tx * 4] = o;
        }
    }
}

// ---------------------------------------------------------------------------
// Pass 1: per-edge score exp(dot(k[src], q[dest]) / 8); accumulate per-graph
// denominator via shared-memory pre-reduction (256 bins) then one flush.
// Warp per edge, grid-stride.  edge_index/batch are int32 (JAX x64 disabled).
// ---------------------------------------------------------------------------
__global__ __launch_bounds__(512) void edge_pass1(
    const int* __restrict__ ei,
    const int* __restrict__ batch)
{
    __shared__ float sden[NG];
    const int tid = threadIdx.x;
    if (tid < NG) sden[tid] = 0.f;
    __syncthreads();

    const int lane = tid & 31;
    int gw = blockIdx.x * (blockDim.x >> 5) + (tid >> 5);
    const int stride = gridDim.x * (blockDim.x >> 5);

    for (int e = gw; e < NE; e += stride) {
        int s = __ldg(&ei[e]);
        int d = __ldg(&ei[NE + e]);
        float2 kk = *(const float2*)&g_k[s * HD + lane * 2];
        float2 qq = *(const float2*)&g_q[d * HD + lane * 2];
        float p = kk.x * qq.x + kk.y * qq.y;
#pragma unroll
        for (int o = 16; o > 0; o >>= 1)
            p += __shfl_xor_sync(0xffffffffu, p, o);
        if (lane == 0) {
            float ex = __expf(p * 0.125f);
            g_ex[e] = ex;
            atomicAdd(&sden[__ldg(&batch[s])], ex);
        }
    }
    __syncthreads();
    if (tid < NG) {
        float v = sden[tid];
        if (v != 0.f) atomicAdd(&g_den[tid], v);
    }
}

// ---------------------------------------------------------------------------
// Pass 2: a = exp / (denom[seg]+1e-6); out[dest] += v[src] * a.
// Warp per edge; each lane issues one red.global.add.v2.f32 (no return).
// ---------------------------------------------------------------------------
__global__ __launch_bounds__(256) void edge_pass2(
    const int* __restrict__ ei,
    const int* __restrict__ batch,
    float* __restrict__ out)
{
    const int lane = threadIdx.x & 31;
    const int e = blockIdx.x * 8 + (threadIdx.x >> 5);
    if (e >= NE) return;

    int s = __ldg(&ei[e]);
    int d = __ldg(&ei[NE + e]);

    float a;
    if (lane == 0)
        a = g_ex[e] / (g_den[__ldg(&batch[s])] + 1e-6f);
    a = __shfl_sync(0xffffffffu, a, 0);

    float2 vv = *(const float2*)&g_v[s * HD + lane * 2];
    float* dst = &out[d * HD + lane * 2];
    asm volatile("red.global.add.v2.f32 [%0], {%1, %2};"
                 :: "l"(dst), "f"(vv.x * a), "f"(vv.y * a)
                 : "memory");
}

// ---------------------------------------------------------------------------
extern "C" void kernel_launch(void* const* d_in, const int* in_sizes, int n_in,
                              void* d_out, int out_size)
{
    const float* x     = (const float*)d_in[0];
    const float* Wq    = (const float*)d_in[1];
    const float* bq    = (const float*)d_in[2];
    const float* Wk    = (const float*)d_in[3];
    const float* bk    = (const float*)d_in[4];
    const float* Wv    = (const float*)d_in[5];
    const float* bv    = (const float*)d_in[6];
    const int*   ei    = (const int*)d_in[7];    // int32: JAX x64 disabled
    const int*   batch = (const int*)d_in[8];    // int32
    float* out = (float*)d_out;

    // Output is accumulated with atomics -> must start at zero.
    cudaMemsetAsync(d_out, 0, (size_t)out_size * sizeof(float));
    zero_den_kernel<<<1, NG>>>();

    dim3 g((NN + 127) / 128, 3);
    qkv_gemm<<<g, 256>>>(x, Wq, bq, Wk, bk, Wv, bv);

    edge_pass1<<<296, 512>>>(ei, batch);
    edge_pass2<<<(NE + 7) / 8, 256>>>(ei, batch, out);
}

// round 3
// speedup vs baseline: 1.3954x; 1.3954x over previous
#include <cuda_runtime.h>

#define NN 50000
#define NE 800000
#define NG 256
#define FIN 256
#define HD 64

__device__ float g_q[NN * HD];
__device__ float g_k[NN * HD];
__device__ float g_v[NN * HD];
__device__ float g_ex[NE];
__device__ float g_den[NG];

// ---------------------------------------------------------------------------
__global__ void zero_den_kernel() { g_den[threadIdx.x] = 0.f; }
__global__ void inv_den_kernel() {
    int i = threadIdx.x;
    g_den[i] = __frcp_rn(g_den[i] + 1e-6f);
}

// ---------------------------------------------------------------------------
// QKV projection GEMM with packed fma.rn.f32x2.
// out[N,64] = x[N,256] @ W[256,64] + b ; blockIdx.y selects {Q,K,V}.
// BM=128, BN=64, BK=16, 128 threads, 8x8 register tile per thread.
// Accumulators are f32x2 pairs (4 pairs per row) -> 32 FFMA2 per k-step.
// ---------------------------------------------------------------------------
__global__ __launch_bounds__(128) void qkv_gemm(
    const float* __restrict__ x,
    const float* __restrict__ Wq, const float* __restrict__ bq,
    const float* __restrict__ Wk, const float* __restrict__ bk,
    const float* __restrict__ Wv, const float* __restrict__ bv)
{
    __shared__ __align__(16) float xs[16][132];  // [k][row], padded
    __shared__ __align__(16) float ws[16][64];   // [k][col]

    const float* W; const float* bias; float* out;
    if (blockIdx.y == 0)      { W = Wq; bias = bq; out = g_q; }
    else if (blockIdx.y == 1) { W = Wk; bias = bk; out = g_k; }
    else                      { W = Wv; bias = bv; out = g_v; }

    const int tid = threadIdx.x;
    const int tx = tid & 7;         // col group: 8 cols
    const int ty = tid >> 3;        // row group: 8 rows (16 groups)
    const int row0 = blockIdx.x * 128;

    unsigned long long acc[8][4];   // 8 rows x 4 col-pairs, f32x2 packed
#pragma unroll
    for (int i = 0; i < 8; i++)
#pragma unroll
        for (int j = 0; j < 4; j++) acc[i][j] = 0ull;

    for (int k0 = 0; k0 < FIN; k0 += 16) {
        // x tile [128 rows x 16 k] -> transposed smem. 4 float4 per thread.
#pragma unroll
        for (int l = 0; l < 4; l++) {
            int idx = tid + l * 128;
            int r  = idx >> 2;
            int kp = idx & 3;
            int grow = row0 + r;
            float4 f = make_float4(0.f, 0.f, 0.f, 0.f);
            if (grow < NN)
                f = *(const float4*)&x[(size_t)grow * FIN + k0 + kp * 4];
            xs[kp * 4 + 0][r] = f.x;
            xs[kp * 4 + 1][r] = f.y;
            xs[kp * 4 + 2][r] = f.z;
            xs[kp * 4 + 3][r] = f.w;
        }
        // W tile [16 k x 64 cols]: 2 float4 per thread.
#pragma unroll
        for (int l = 0; l < 2; l++) {
            int idx = tid + l * 128;
            int r  = idx >> 4;
            int c4 = idx & 15;
            *(float4*)&ws[r][c4 * 4] =
                *(const float4*)&W[(size_t)(k0 + r) * HD + c4 * 4];
        }
        __syncthreads();

#pragma unroll
        for (int kk = 0; kk < 16; kk++) {
            float4 a0 = *(const float4*)&xs[kk][ty * 8];
            float4 a1 = *(const float4*)&xs[kk][ty * 8 + 4];
            float4 b0 = *(const float4*)&ws[kk][tx * 8];
            float4 b1 = *(const float4*)&ws[kk][tx * 8 + 4];
            unsigned long long bp[4];
            asm("mov.b64 %0, {%1, %2};" : "=l"(bp[0]) : "f"(b0.x), "f"(b0.y));
            asm("mov.b64 %0, {%1, %2};" : "=l"(bp[1]) : "f"(b0.z), "f"(b0.w));
            asm("mov.b64 %0, {%1, %2};" : "=l"(bp[2]) : "f"(b1.x), "f"(b1.y));
            asm("mov.b64 %0, {%1, %2};" : "=l"(bp[3]) : "f"(b1.z), "f"(b1.w));
            float av[8] = {a0.x, a0.y, a0.z, a0.w, a1.x, a1.y, a1.z, a1.w};
#pragma unroll
            for (int i = 0; i < 8; i++) {
                unsigned long long ad;
                asm("mov.b64 %0, {%1, %1};" : "=l"(ad) : "f"(av[i]));
#pragma unroll
                for (int j = 0; j < 4; j++)
                    asm("fma.rn.f32x2 %0, %1, %2, %0;"
                        : "+l"(acc[i][j]) : "l"(ad), "l"(bp[j]));
            }
        }
        __syncthreads();
    }

    float4 bias0 = *(const float4*)&bias[tx * 8];
    float4 bias1 = *(const float4*)&bias[tx * 8 + 4];
#pragma unroll
    for (int i = 0; i < 8; i++) {
        int grow = row0 + ty * 8 + i;
        if (grow < NN) {
            float r[8];
#pragma unroll
            for (int j = 0; j < 4; j++)
                asm("mov.b64 {%0, %1}, %2;"
                    : "=f"(r[j * 2]), "=f"(r[j * 2 + 1]) : "l"(acc[i][j]));
            float4 o0 = make_float4(r[0] + bias0.x, r[1] + bias0.y,
                                    r[2] + bias0.z, r[3] + bias0.w);
            float4 o1 = make_float4(r[4] + bias1.x, r[5] + bias1.y,
                                    r[6] + bias1.z, r[7] + bias1.w);
            *(float4*)&out[(size_t)grow * HD + tx * 8]     = o0;
            *(float4*)&out[(size_t)grow * HD + tx * 8 + 4] = o1;
        }
    }
}

// ---------------------------------------------------------------------------
// Pass 1: ex[e] = exp(dot(k[src], q[dest]) / 8); per-graph denominator into
// shared bins, one global flush per block. 2 edges per warp (16 lanes each,
// float4 per lane). Grid-stride.
// ---------------------------------------------------------------------------
__global__ __launch_bounds__(512) void edge_pass1(
    const int* __restrict__ ei,
    const int* __restrict__ batch)
{
    __shared__ float sden[NG];
    const int tid = threadIdx.x;
    if (tid < NG) sden[tid] = 0.f;
    __syncthreads();

    const int lane = tid & 31;
    const int half = lane >> 4;
    const int hl   = lane & 15;
    const int w = blockIdx.x * 16 + (tid >> 5);
    const int stride = gridDim.x * 16 * 2;

    for (int e = w * 2 + half; e < NE; e += stride) {
        int s = __ldg(&ei[e]);
        int d = __ldg(&ei[NE + e]);
        float4 kk = *(const float4*)&g_k[s * HD + hl * 4];
        float4 qq = *(const float4*)&g_q[d * HD + hl * 4];
        float p = kk.x * qq.x + kk.y * qq.y + kk.z * qq.z + kk.w * qq.w;
#pragma unroll
        for (int o = 8; o > 0; o >>= 1)
            p += __shfl_xor_sync(0xffffffffu, p, o);
        if (hl == 0) {
            float ex = __expf(p * 0.125f);
            g_ex[e] = ex;
            atomicAdd(&sden[__ldg(&batch[s])], ex);
        }
    }
    __syncthreads();
    if (tid < NG) {
        float v = sden[tid];
        if (v != 0.f) atomicAdd(&g_den[tid], v);
    }
}

// ---------------------------------------------------------------------------
// Pass 2: a = ex[e] * inv_den[seg]; out[dest] += v[src] * a.
// 2 edges per warp, 16 lanes x float4 each, red.global.add.v4.f32.
// ---------------------------------------------------------------------------
__global__ __launch_bounds__(256) void edge_pass2(
    const int* __restrict__ ei,
    const int* __restrict__ batch,
    float* __restrict__ out)
{
    const int lane = threadIdx.x & 31;
    const int half = lane >> 4;
    const int hl   = lane & 15;
    const int e = (blockIdx.x * 8 + (threadIdx.x >> 5)) * 2 + half;
    if (e >= NE) return;

    int s = __ldg(&ei[e]);
    int d = __ldg(&ei[NE + e]);

    float a = 0.f;
    if (hl == 0)
        a = g_ex[e] * g_den[__ldg(&batch[s])];   // g_den holds 1/(den+eps)
    a = __shfl_sync(0xffffffffu, a, half << 4);

    float4 vv = *(const float4*)&g_v[s * HD + hl * 4];
    float* dst = &out[d * HD + hl * 4];
    asm volatile("red.global.add.v4.f32 [%0], {%1, %2, %3, %4};"
                 :: "l"(dst), "f"(vv.x * a), "f"(vv.y * a),
                    "f"(vv.z * a), "f"(vv.w * a)
                 : "memory");
}

// ---------------------------------------------------------------------------
extern "C" void kernel_launch(void* const* d_in, const int* in_sizes, int n_in,
                              void* d_out, int out_size)
{
    const float* x     = (const float*)d_in[0];
    const float* Wq    = (const float*)d_in[1];
    const float* bq    = (const float*)d_in[2];
    const float* Wk    = (const float*)d_in[3];
    const float* bk    = (const float*)d_in[4];
    const float* Wv    = (const float*)d_in[5];
    const float* bv    = (const float*)d_in[6];
    const int*   ei    = (const int*)d_in[7];    // int32 (JAX x64 disabled)
    const int*   batch = (const int*)d_in[8];
    float* out = (float*)d_out;

    cudaMemsetAsync(d_out, 0, (size_t)out_size * sizeof(float));
    zero_den_kernel<<<1, NG>>>();

    dim3 g((NN + 127) / 128, 3);
    qkv_gemm<<<g, 128>>>(x, Wq, bq, Wk, bk, Wv, bv);

    edge_pass1<<<296, 512>>>(ei, batch);
    inv_den_kernel<<<1, NG>>>();
    edge_pass2<<<NE / 16, 256>>>(ei, batch, out);
}